// round 13
// baseline (speedup 1.0000x reference)
#include <cuda_runtime.h>
#include <cstdint>

#define NBOX   8192
#define WORDS  128
#define CAP    32           // per-row predecessor capacity
#define SCAP   8            // predecessors cached in shared per row
#define GRID   64           // 32-px cells over 2048 px
#define NCELL  (GRID * GRID)
#define CAPC   32           // boxes per cell capacity
#define DETF   (NBOX * 9)   // 73728 floats
#define RPNF   (NBOX * 6)   // 49152 floats

// ---------------------------------------------------------------------------
// Persistent scratch (device globals — no runtime allocation).
// ---------------------------------------------------------------------------
__device__ int            g_ccnt[2][NCELL];
__device__ float4         g_cellbox[2][NCELL][CAPC];   // x1,y1,x2,y2
__device__ unsigned short g_cellidx[2][NCELL][CAPC];   // box index
__device__ int            g_cnt[2][NBOX];              // per-row pred count
__device__ unsigned short g_adj[2][NBOX][CAP];         // predecessors (j < i)

// ---------------------------------------------------------------------------
// K1: bin boxes into 32-px cells. One thread per (set, box).
// ---------------------------------------------------------------------------
__global__ void bin_kernel(const float* __restrict__ det,
                           const float* __restrict__ rpn) {
    const int t = blockIdx.x * blockDim.x + threadIdx.x;
    if (t >= 2 * NBOX) return;
    const int s = t >> 13;
    const int i = t & (NBOX - 1);
    const float* __restrict__ p = s ? rpn : det;
    const int stride = s ? 6 : 9;

    const float* q = p + i * stride + 1;
    const float x1 = q[0], y1 = q[1], x2 = q[2], y2 = q[3];
    const float cx = 0.5f * (x1 + x2);
    const float cy = 0.5f * (y1 + y2);

    int gx = (int)(cx * (1.0f / 32.0f)); gx = min(max(gx, 0), GRID - 1);
    int gy = (int)(cy * (1.0f / 32.0f)); gy = min(max(gy, 0), GRID - 1);
    const int cell = gy * GRID + gx;

    const int pos = atomicAdd(&g_ccnt[s][cell], 1);
    if (pos < CAPC) {
        g_cellbox[s][cell][pos] = make_float4(x1, y1, x2, y2);
        g_cellidx[s][cell][pos] = (unsigned short)i;
    }
}

// ---------------------------------------------------------------------------
// K2: predecessor extraction via 3x3 cell neighborhood.
// Prune bound: IoU>0.6 => |dcx|,|dcy| < 0.125*(w1+w2) <= 30 px.
// Index loaded first (2B) to reject j>=i before the 16B box load.
// ---------------------------------------------------------------------------
__global__ void edge_kernel(const float* __restrict__ det,
                            const float* __restrict__ rpn) {
    const int t = blockIdx.x * blockDim.x + threadIdx.x;
    if (t >= 2 * NBOX) return;
    const int s = t >> 13;
    const int i = t & (NBOX - 1);
    const float* __restrict__ p = s ? rpn : det;
    const int stride = s ? 6 : 9;

    const float* q = p + i * stride + 1;
    const float ax1 = q[0], ay1 = q[1], ax2 = q[2], ay2 = q[3];
    const float axs = ax1 + ax2;                 // 2*cx
    const float ays = ay1 + ay2;
    const float aA  = 0.375f * ((ax2 - ax1) * (ay2 - ay1));

    int gx = (int)(axs * (1.0f / 64.0f)); gx = min(max(gx, 0), GRID - 1);
    int gy = (int)(ays * (1.0f / 64.0f)); gy = min(max(gy, 0), GRID - 1);

    int cnt = 0;
    #pragma unroll
    for (int dy = -1; dy <= 1; dy++) {
        const int yy = gy + dy;
        if (yy < 0 || yy >= GRID) continue;
        #pragma unroll
        for (int dx = -1; dx <= 1; dx++) {
            const int xx = gx + dx;
            if (xx < 0 || xx >= GRID) continue;
            const int cell = yy * GRID + xx;
            int n = g_ccnt[s][cell];
            n = min(n, CAPC);
            for (int k = 0; k < n; k++) {
                const int j = g_cellidx[s][cell][k];
                if (j >= i) continue;                       // preds only
                const float4 b = g_cellbox[s][cell][k];
                if (fabsf(b.x + b.z - axs) < 62.0f &&       // |dcx| < 31
                    fabsf(b.y + b.w - ays) < 62.0f) {
                    const float iw = fminf(ax2, b.z) - fmaxf(ax1, b.x);
                    const float ih = fminf(ay2, b.w) - fmaxf(ay1, b.y);
                    const float inter = fmaxf(iw, 0.f) * fmaxf(ih, 0.f);
                    const float bA = 0.375f * ((b.z - b.x) * (b.w - b.y));
                    if (inter > aA + bA) {                  // iou > 0.6
                        if (cnt < CAP) g_adj[s][i][cnt] = (unsigned short)j;
                        cnt++;
                    }
                }
            }
        }
    }
    g_cnt[s][i] = min(cnt, CAP);
}

// ---------------------------------------------------------------------------
// K3: NMS fixpoint + fused output.
// grid 2 (block s = set s), 1024 threads.
//  - stage predecessor lists + compact active-row list
//  - parallel Gauss-Seidel sweeps over active list until stable
//  - block 0 writes [valid det][invalid det], block 1 writes [rpn] segment.
// Shared: shAdj region (128KB) reused as score scratch after sweeps.
// ---------------------------------------------------------------------------
#define OFF_ADJ   0
#define OFF_CNT   (NBOX * 16)
#define OFF_S     (OFF_CNT + NBOX)
#define OFF_T0    (OFF_S + NBOX)
#define OFF_LIST  (OFF_T0 + NBOX)
#define OFF_INT   (OFF_LIST + NBOX * 2)
#define NMS_SMEM  (OFF_INT + 16)

__global__ void nms_out_kernel(const float* __restrict__ det,
                               const float* __restrict__ rpn,
                               float* __restrict__ out) {
    const int s = blockIdx.x;
    extern __shared__ unsigned char sm[];
    uint4*          shAdj  = (uint4*)(sm + OFF_ADJ);             // [NBOX]
    float*          shSc   = (float*)(sm + OFF_ADJ);             // reuse post-sweep
    unsigned char*  shCnt  = sm + OFF_CNT;                       // [NBOX]
    unsigned char*  shS    = sm + OFF_S;                         // [NBOX]
    unsigned char*  shT0   = sm + OFF_T0;                        // [NBOX]
    unsigned short* shList = (unsigned short*)(sm + OFF_LIST);   // [NBOX]
    int*            shNact = (int*)(sm + OFF_INT);
    int*            shChg  = (int*)(sm + OFF_INT + 4);

    const int tid = threadIdx.x;
    if (tid == 0) *shNact = 0;
    __syncthreads();

    // ---- stage predecessor lists + active list ----
    for (int b = 0; b < NBOX / 1024; b++) {
        const int r = b * 1024 + tid;
        int c = g_cnt[s][r];
        c = min(c, CAP);
        shCnt[r] = (unsigned char)c;
        shS[r] = 0;
        if (c > 0) {
            shAdj[r] = *(const uint4*)&g_adj[s][r][0];
            const int pos = atomicAdd(shNact, 1);
            shList[pos] = (unsigned short)r;
        }
    }
    __syncthreads();
    const int nact = *shNact;

    // ---- chaotic Gauss-Seidel sweeps until stable (unique DAG fixpoint) ----
    for (;;) {
        if (tid == 0) *shChg = 0;
        __syncthreads();
        for (int t = tid; t < nact; t += 1024) {
            const int r = shList[t];
            const int c = shCnt[r];
            const unsigned short* pe = (const unsigned short*)(shAdj + r);
            unsigned char sup = 0;
            for (int k = 0; k < c; k++) {
                const int p = (k < SCAP) ? (int)pe[k] : (int)g_adj[s][r][k];
                sup |= (shS[p] == 0) ? 1 : 0;
            }
            if (sup != shS[r]) { shS[r] = sup; *shChg = 1; }
        }
        __syncthreads();
        if (*shChg == 0) break;
        __syncthreads();
    }
    // shS[r] == 0  <=>  box r kept.

    // ---- fused output ----
    if (s == 1) {
        // rpn segment: out[147456 .. 196608)
        const float4* __restrict__ rp4 = (const float4*)rpn;
        float4* __restrict__ o4 = (float4*)(out + 2 * DETF);
        for (int k4 = tid; k4 < RPNF / 4; k4 += 1024) {
            float4 v = rp4[k4];
            const int k = k4 * 4;
            float* vv = (float*)&v;
            #pragma unroll
            for (int e = 0; e < 4; e++) {
                const int r = (k + e) / 6;
                if (shS[r]) vv[e] = 0.f;
            }
            o4[k4] = v;
        }
        return;
    }

    // block 0: det segments. Pass 1: coalesced score gather into shSc.
    // (overwrites shAdj — sweeps are complete)
    for (int idx = tid; idx < DETF; idx += 1024) {
        const float val = det[idx];
        const int r = idx / 9;
        const int c = idx - r * 9;
        if (c >= 5) shSc[r * 4 + (c - 5)] = val;
    }
    __syncthreads();

    // Pass 2: per-row first-max argmax -> t0 flag
    for (int b = 0; b < NBOX / 1024; b++) {
        const int r = b * 1024 + tid;
        const float s5 = shSc[r * 4 + 0];
        const float s6 = shSc[r * 4 + 1];
        const float s7 = shSc[r * 4 + 2];
        const float s8 = shSc[r * 4 + 3];
        const bool t0 = !(s6 > s5) && !(s7 > fmaxf(s5, s6)) &&
                        !(s8 > fmaxf(fmaxf(s5, s6), s7));
        shT0[r] = t0 ? 1 : 0;
    }
    __syncthreads();

    // Pass 3: masked writes, float4-vectorized. out[0..147456)
    {
        float4* __restrict__ o4 = (float4*)out;
        for (int k4 = tid; k4 < (2 * DETF) / 4; k4 += 1024) {
            const int k = k4 * 4;
            float4 v;
            float* vv = (float*)&v;
            #pragma unroll
            for (int e = 0; e < 4; e++) {
                const int ko = k + e;
                const bool seg = (ko >= DETF);          // invalid segment?
                const int kk = seg ? ko - DETF : ko;
                const int r = kk / 9;
                const bool keep = (shS[r] == 0);
                const bool t0 = shT0[r] != 0;
                const bool pick = keep && (seg ? t0 : !t0);
                vv[e] = pick ? det[kk] : 0.f;
            }
            o4[k4] = v;
        }
    }
}

// ---------------------------------------------------------------------------
extern "C" void kernel_launch(void* const* d_in, const int* in_sizes, int n_in,
                              void* d_out, int out_size) {
    const float* det;
    const float* rpn;
    if (in_sizes[0] == NBOX * 9) {
        det = (const float*)d_in[0];
        rpn = (const float*)d_in[1];
    } else {
        det = (const float*)d_in[1];
        rpn = (const float*)d_in[0];
    }
    float* out = (float*)d_out;

    cudaFuncSetAttribute(nms_out_kernel,
                         cudaFuncAttributeMaxDynamicSharedMemorySize, NMS_SMEM);

    // zero cell counters via graph memset node (replaces zero_kernel launch)
    void* ccnt_ptr = nullptr;
    cudaGetSymbolAddress(&ccnt_ptr, g_ccnt);
    cudaMemsetAsync(ccnt_ptr, 0, sizeof(int) * 2 * NCELL, 0);

    bin_kernel<<<(2 * NBOX + 255) / 256, 256>>>(det, rpn);
    edge_kernel<<<(2 * NBOX + 255) / 256, 256>>>(det, rpn);
    nms_out_kernel<<<2, 1024, NMS_SMEM>>>(det, rpn, out);
}

// round 17
// speedup vs baseline: 1.0010x; 1.0010x over previous
#include <cuda_runtime.h>
#include <cstdint>

#define NBOX   8192
#define WORDS  128
#define CAP    32           // per-row predecessor capacity
#define SCAP   8            // predecessors cached in shared per row
#define GRID   64           // 32-px cells over 2048 px
#define NCELL  (GRID * GRID)
#define CAPC   32           // boxes per cell capacity
#define DETF   (NBOX * 9)   // 73728 floats
#define RPNF   (NBOX * 6)   // 49152 floats

// ---------------------------------------------------------------------------
// Persistent scratch (device globals — no runtime allocation).
// ---------------------------------------------------------------------------
__device__ int            g_ccnt[2][NCELL];
__device__ float4         g_cellbox[2][NCELL][CAPC];   // x1,y1,x2,y2
__device__ unsigned short g_cellidx[2][NCELL][CAPC];   // box index
__device__ int            g_cnt[2][NBOX];              // per-row pred count
__device__ unsigned short g_adj[2][NBOX][CAP];         // predecessors (j < i)

// ---------------------------------------------------------------------------
// K1: bin boxes into 32-px cells. One thread per (set, box).
// ---------------------------------------------------------------------------
__global__ void bin_kernel(const float* __restrict__ det,
                           const float* __restrict__ rpn) {
    const int t = blockIdx.x * blockDim.x + threadIdx.x;
    if (t >= 2 * NBOX) return;
    const int s = t >> 13;
    const int i = t & (NBOX - 1);
    const float* __restrict__ p = s ? rpn : det;
    const int stride = s ? 6 : 9;

    const float* q = p + i * stride + 1;
    const float x1 = q[0], y1 = q[1], x2 = q[2], y2 = q[3];
    const float cx = 0.5f * (x1 + x2);
    const float cy = 0.5f * (y1 + y2);

    int gx = (int)(cx * (1.0f / 32.0f)); gx = min(max(gx, 0), GRID - 1);
    int gy = (int)(cy * (1.0f / 32.0f)); gy = min(max(gy, 0), GRID - 1);
    const int cell = gy * GRID + gx;

    const int pos = atomicAdd(&g_ccnt[s][cell], 1);
    if (pos < CAPC) {
        g_cellbox[s][cell][pos] = make_float4(x1, y1, x2, y2);
        g_cellidx[s][cell][pos] = (unsigned short)i;
    }
}

// ---------------------------------------------------------------------------
// K2: predecessor extraction via 3x3 cell neighborhood.
// Prune bound: IoU>0.6 => |dcx|,|dcy| < 0.125*(w1+w2) <= 30 px.
// Index loaded first (2B) to reject j>=i before the 16B box load.
// ---------------------------------------------------------------------------
__global__ void edge_kernel(const float* __restrict__ det,
                            const float* __restrict__ rpn) {
    const int t = blockIdx.x * blockDim.x + threadIdx.x;
    if (t >= 2 * NBOX) return;
    const int s = t >> 13;
    const int i = t & (NBOX - 1);
    const float* __restrict__ p = s ? rpn : det;
    const int stride = s ? 6 : 9;

    const float* q = p + i * stride + 1;
    const float ax1 = q[0], ay1 = q[1], ax2 = q[2], ay2 = q[3];
    const float axs = ax1 + ax2;                 // 2*cx
    const float ays = ay1 + ay2;
    const float aA  = 0.375f * ((ax2 - ax1) * (ay2 - ay1));

    int gx = (int)(axs * (1.0f / 64.0f)); gx = min(max(gx, 0), GRID - 1);
    int gy = (int)(ays * (1.0f / 64.0f)); gy = min(max(gy, 0), GRID - 1);

    int cnt = 0;
    #pragma unroll
    for (int dy = -1; dy <= 1; dy++) {
        const int yy = gy + dy;
        if (yy < 0 || yy >= GRID) continue;
        #pragma unroll
        for (int dx = -1; dx <= 1; dx++) {
            const int xx = gx + dx;
            if (xx < 0 || xx >= GRID) continue;
            const int cell = yy * GRID + xx;
            int n = g_ccnt[s][cell];
            n = min(n, CAPC);
            for (int k = 0; k < n; k++) {
                const int j = g_cellidx[s][cell][k];
                if (j >= i) continue;                       // preds only
                const float4 b = g_cellbox[s][cell][k];
                if (fabsf(b.x + b.z - axs) < 62.0f &&       // |dcx| < 31
                    fabsf(b.y + b.w - ays) < 62.0f) {
                    const float iw = fminf(ax2, b.z) - fmaxf(ax1, b.x);
                    const float ih = fminf(ay2, b.w) - fmaxf(ay1, b.y);
                    const float inter = fmaxf(iw, 0.f) * fmaxf(ih, 0.f);
                    const float bA = 0.375f * ((b.z - b.x) * (b.w - b.y));
                    if (inter > aA + bA) {                  // iou > 0.6
                        if (cnt < CAP) g_adj[s][i][cnt] = (unsigned short)j;
                        cnt++;
                    }
                }
            }
        }
    }
    g_cnt[s][i] = min(cnt, CAP);
}

// ---------------------------------------------------------------------------
// K3: NMS fixpoint + fused output.
// grid 2 (block s = set s), 1024 threads.
//  - stage predecessor lists + compact active-row list
//  - parallel Gauss-Seidel sweeps over active list until stable
//  - block 0 writes [valid det][invalid det], block 1 writes [rpn] segment.
// Shared: shAdj region (128KB) reused as score scratch after sweeps.
// ---------------------------------------------------------------------------
#define OFF_ADJ   0
#define OFF_CNT   (NBOX * 16)
#define OFF_S     (OFF_CNT + NBOX)
#define OFF_T0    (OFF_S + NBOX)
#define OFF_LIST  (OFF_T0 + NBOX)
#define OFF_INT   (OFF_LIST + NBOX * 2)
#define NMS_SMEM  (OFF_INT + 16)

__global__ void nms_out_kernel(const float* __restrict__ det,
                               const float* __restrict__ rpn,
                               float* __restrict__ out) {
    const int s = blockIdx.x;
    extern __shared__ unsigned char sm[];
    uint4*          shAdj  = (uint4*)(sm + OFF_ADJ);             // [NBOX]
    float*          shSc   = (float*)(sm + OFF_ADJ);             // reuse post-sweep
    unsigned char*  shCnt  = sm + OFF_CNT;                       // [NBOX]
    unsigned char*  shS    = sm + OFF_S;                         // [NBOX]
    unsigned char*  shT0   = sm + OFF_T0;                        // [NBOX]
    unsigned short* shList = (unsigned short*)(sm + OFF_LIST);   // [NBOX]
    int*            shNact = (int*)(sm + OFF_INT);
    int*            shChg  = (int*)(sm + OFF_INT + 4);

    const int tid = threadIdx.x;
    if (tid == 0) *shNact = 0;
    __syncthreads();

    // ---- stage predecessor lists + active list ----
    for (int b = 0; b < NBOX / 1024; b++) {
        const int r = b * 1024 + tid;
        int c = g_cnt[s][r];
        c = min(c, CAP);
        shCnt[r] = (unsigned char)c;
        shS[r] = 0;
        if (c > 0) {
            shAdj[r] = *(const uint4*)&g_adj[s][r][0];
            const int pos = atomicAdd(shNact, 1);
            shList[pos] = (unsigned short)r;
        }
    }
    __syncthreads();
    const int nact = *shNact;

    // ---- chaotic Gauss-Seidel sweeps until stable (unique DAG fixpoint) ----
    for (;;) {
        if (tid == 0) *shChg = 0;
        __syncthreads();
        for (int t = tid; t < nact; t += 1024) {
            const int r = shList[t];
            const int c = shCnt[r];
            const unsigned short* pe = (const unsigned short*)(shAdj + r);
            unsigned char sup = 0;
            for (int k = 0; k < c; k++) {
                const int p = (k < SCAP) ? (int)pe[k] : (int)g_adj[s][r][k];
                sup |= (shS[p] == 0) ? 1 : 0;
            }
            if (sup != shS[r]) { shS[r] = sup; *shChg = 1; }
        }
        __syncthreads();
        if (*shChg == 0) break;
        __syncthreads();
    }
    // shS[r] == 0  <=>  box r kept.

    // ---- fused output ----
    if (s == 1) {
        // rpn segment: out[147456 .. 196608)
        const float4* __restrict__ rp4 = (const float4*)rpn;
        float4* __restrict__ o4 = (float4*)(out + 2 * DETF);
        for (int k4 = tid; k4 < RPNF / 4; k4 += 1024) {
            float4 v = rp4[k4];
            const int k = k4 * 4;
            float* vv = (float*)&v;
            #pragma unroll
            for (int e = 0; e < 4; e++) {
                const int r = (k + e) / 6;
                if (shS[r]) vv[e] = 0.f;
            }
            o4[k4] = v;
        }
        return;
    }

    // block 0: det segments. Pass 1: coalesced score gather into shSc.
    // (overwrites shAdj — sweeps are complete)
    for (int idx = tid; idx < DETF; idx += 1024) {
        const float val = det[idx];
        const int r = idx / 9;
        const int c = idx - r * 9;
        if (c >= 5) shSc[r * 4 + (c - 5)] = val;
    }
    __syncthreads();

    // Pass 2: per-row first-max argmax -> t0 flag
    for (int b = 0; b < NBOX / 1024; b++) {
        const int r = b * 1024 + tid;
        const float s5 = shSc[r * 4 + 0];
        const float s6 = shSc[r * 4 + 1];
        const float s7 = shSc[r * 4 + 2];
        const float s8 = shSc[r * 4 + 3];
        const bool t0 = !(s6 > s5) && !(s7 > fmaxf(s5, s6)) &&
                        !(s8 > fmaxf(fmaxf(s5, s6), s7));
        shT0[r] = t0 ? 1 : 0;
    }
    __syncthreads();

    // Pass 3: masked writes, float4-vectorized. out[0..147456)
    {
        float4* __restrict__ o4 = (float4*)out;
        for (int k4 = tid; k4 < (2 * DETF) / 4; k4 += 1024) {
            const int k = k4 * 4;
            float4 v;
            float* vv = (float*)&v;
            #pragma unroll
            for (int e = 0; e < 4; e++) {
                const int ko = k + e;
                const bool seg = (ko >= DETF);          // invalid segment?
                const int kk = seg ? ko - DETF : ko;
                const int r = kk / 9;
                const bool keep = (shS[r] == 0);
                const bool t0 = shT0[r] != 0;
                const bool pick = keep && (seg ? t0 : !t0);
                vv[e] = pick ? det[kk] : 0.f;
            }
            o4[k4] = v;
        }
    }
}

// ---------------------------------------------------------------------------
extern "C" void kernel_launch(void* const* d_in, const int* in_sizes, int n_in,
                              void* d_out, int out_size) {
    const float* det;
    const float* rpn;
    if (in_sizes[0] == NBOX * 9) {
        det = (const float*)d_in[0];
        rpn = (const float*)d_in[1];
    } else {
        det = (const float*)d_in[1];
        rpn = (const float*)d_in[0];
    }
    float* out = (float*)d_out;

    cudaFuncSetAttribute(nms_out_kernel,
                         cudaFuncAttributeMaxDynamicSharedMemorySize, NMS_SMEM);

    // zero cell counters via graph memset node (replaces zero_kernel launch)
    void* ccnt_ptr = nullptr;
    cudaGetSymbolAddress(&ccnt_ptr, g_ccnt);
    cudaMemsetAsync(ccnt_ptr, 0, sizeof(int) * 2 * NCELL, 0);

    bin_kernel<<<(2 * NBOX + 255) / 256, 256>>>(det, rpn);
    edge_kernel<<<(2 * NBOX + 255) / 256, 256>>>(det, rpn);
    nms_out_kernel<<<2, 1024, NMS_SMEM>>>(det, rpn, out);
}